// round 9
// baseline (speedup 1.0000x reference)
#include <cuda_runtime.h>
#include <cuda_fp16.h>
#include <math.h>
#include <stdint.h>

#define S_TOT 8192           // T*H*W = 8*32*32
#define CCH   512
#define NELEM (CCH * S_TOT)  // 4,194,304
#define PAD_PER_C 11560      // 10*34*34
#define KDIM 13824           // 512*27
#define KT32 432             // KDIM/32

// ---------------- scratch (device globals: allocation-free) ----------------
__device__ float g_buf0[NELEM];
__device__ float g_buf1[NELEM];
__device__ float g_buf2[NELEM];
__device__ float g_q[NELEM];      // half Q (uses half the space)
__device__ float g_k[NELEM];
__device__ float g_v[NELEM];
__device__ float g_scores[(size_t)S_TOT * S_TOT];  // 256 MB
__device__ float g_pad[CCH * PAD_PER_C];           // (half) padded conv input
__device__ uint32_t g_wfr[KDIM * CCH / 2];         // fp16 fragment-packed weights
__device__ int   g_offB[KDIM];                     // per-k pad offset table
__device__ float2 g_part[256];
__device__ float g_mean[32];
__device__ float g_rstd[32];

// ---------------- MMA primitives -------------------------------------------
__device__ __forceinline__ void mma_tf32(float c[4], uint32_t a0, uint32_t a1,
                                         uint32_t a2, uint32_t a3,
                                         uint32_t b0, uint32_t b1) {
    asm volatile(
        "mma.sync.aligned.m16n8k8.row.col.f32.tf32.tf32.f32 "
        "{%0,%1,%2,%3}, {%4,%5,%6,%7}, {%8,%9}, {%0,%1,%2,%3};\n"
        : "+f"(c[0]), "+f"(c[1]), "+f"(c[2]), "+f"(c[3])
        : "r"(a0), "r"(a1), "r"(a2), "r"(a3), "r"(b0), "r"(b1));
}
__device__ __forceinline__ void mma_f16(float c[4], uint32_t a0, uint32_t a1,
                                        uint32_t a2, uint32_t a3,
                                        uint32_t b0, uint32_t b1) {
    asm volatile(
        "mma.sync.aligned.m16n8k16.row.col.f32.f16.f16.f32 "
        "{%0,%1,%2,%3}, {%4,%5,%6,%7}, {%8,%9}, {%0,%1,%2,%3};\n"
        : "+f"(c[0]), "+f"(c[1]), "+f"(c[2]), "+f"(c[3])
        : "r"(a0), "r"(a1), "r"(a2), "r"(a3), "r"(b0), "r"(b1));
}
__device__ __forceinline__ uint32_t f2tf32(float x) {
    uint32_t r;
    asm("cvt.rna.tf32.f32 %0, %1;" : "=r"(r) : "f"(x));
    return r;
}
__device__ __forceinline__ uint32_t f2h2(float lo, float hi) {
    __half2 h = __floats2half2_rn(lo, hi);
    return *(uint32_t*)&h;
}
__device__ __forceinline__ uint32_t pkh2(__half lo, __half hi) {
    return (uint32_t)__half_as_ushort(lo) | ((uint32_t)__half_as_ushort(hi) << 16);
}

// matrix-order tf32 warp-tile compute (pv kernel)
#define MMA_COMPUTE(buf)                                                     \
    _Pragma("unroll")                                                        \
    for (int ks = 0; ks < 2; ks++) {                                         \
        uint32_t af[4][4], bf[4][2];                                         \
        _Pragma("unroll")                                                    \
        for (int i2 = 0; i2 < 4; i2++) {                                     \
            af[i2][0] = As[buf][ks * 8 + tig][mw + i2 * 16 + grp];           \
            af[i2][1] = As[buf][ks * 8 + tig][mw + i2 * 16 + grp + 8];       \
            af[i2][2] = As[buf][ks * 8 + tig + 4][mw + i2 * 16 + grp];       \
            af[i2][3] = As[buf][ks * 8 + tig + 4][mw + i2 * 16 + grp + 8];   \
        }                                                                    \
        _Pragma("unroll")                                                    \
        for (int j2 = 0; j2 < 4; j2++) {                                     \
            bf[j2][0] = Bs[buf][ks * 8 + tig][nw + j2 * 8 + grp];            \
            bf[j2][1] = Bs[buf][ks * 8 + tig + 4][nw + j2 * 8 + grp];        \
        }                                                                    \
        _Pragma("unroll")                                                    \
        for (int i2 = 0; i2 < 4; i2++)                                       \
            _Pragma("unroll")                                                \
            for (int j2 = 0; j2 < 4; j2++)                                   \
                mma_tf32(c[i2][j2], af[i2][0], af[i2][1], af[i2][2],         \
                         af[i2][3], bf[j2][0], bf[j2][1]);                   \
    }

// fragment-layout fp16 warp-tile compute (conv/proj/scores); A stride AS
#define HMMA_TILE(Asm_, Bsm_, buf, AS)                                       \
    _Pragma("unroll")                                                        \
    for (int ks = 0; ks < 2; ks++) {                                         \
        uint4 av[4];                                                         \
        uint2 bv2[4];                                                        \
        _Pragma("unroll")                                                    \
        for (int i2 = 0; i2 < 4; i2++)                                       \
            av[i2] = *(const uint4*)&Asm_[buf][(ks * 8 + mt0 + i2) * AS + lane * 4]; \
        _Pragma("unroll")                                                    \
        for (int j2 = 0; j2 < 4; j2++)                                       \
            bv2[j2] = *(const uint2*)&Bsm_[buf][(ks * 16 + nt0 + j2) * 66 + lane * 2]; \
        _Pragma("unroll")                                                    \
        for (int i2 = 0; i2 < 4; i2++)                                       \
            _Pragma("unroll")                                                \
            for (int j2 = 0; j2 < 4; j2++)                                   \
                mma_f16(c[i2][j2], av[i2].x, av[i2].y, av[i2].z, av[i2].w,   \
                        bv2[j2].x, bv2[j2].y);                               \
    }

// ---------------- GroupNorm stats: partial + finalize -----------------------
__global__ void gn_part_kernel(const float* __restrict__ x) {
    __shared__ float rs[256], rq[256];
    int g = blockIdx.x >> 3, ch = blockIdx.x & 7;
    const float* base = x + (size_t)g * 16 * S_TOT + ch * 16384;
    float s = 0.f, ss = 0.f;
    for (int i = threadIdx.x; i < 16384; i += 256) {
        float v = base[i];
        s += v;
        ss += v * v;
    }
    rs[threadIdx.x] = s;
    rq[threadIdx.x] = ss;
    __syncthreads();
    for (int off = 128; off > 0; off >>= 1) {
        if (threadIdx.x < off) {
            rs[threadIdx.x] += rs[threadIdx.x + off];
            rq[threadIdx.x] += rq[threadIdx.x + off];
        }
        __syncthreads();
    }
    if (threadIdx.x == 0) g_part[blockIdx.x] = make_float2(rs[0], rq[0]);
}

__global__ void gn_fin_kernel() {
    int g = threadIdx.x;
    if (g < 32) {
        float s = 0.f, ss = 0.f;
        for (int c = 0; c < 8; c++) {
            float2 p = g_part[g * 8 + c];
            s += p.x;
            ss += p.y;
        }
        float mean = s * (1.f / 131072.f);
        float var = ss * (1.f / 131072.f) - mean * mean;
        g_mean[g] = mean;
        g_rstd[g] = rsqrtf(var + 1e-6f);
    }
}

// ---------------- GroupNorm apply (fp32 out, attention path) ----------------
__global__ void gn_apply_kernel(const float* __restrict__ x, float* __restrict__ y,
                                const float* __restrict__ sc, const float* __restrict__ bi) {
    int i4 = blockIdx.x * blockDim.x + threadIdx.x;
    int c = i4 >> 11;
    int g = c >> 4;
    float rstd = g_rstd[g];
    float a = sc[c] * rstd;
    float b = bi[c] - g_mean[g] * a;
    float4 v = ((const float4*)x)[i4];
    float4 r;
    r.x = a * v.x + b;
    r.y = a * v.y + b;
    r.z = a * v.z + b;
    r.w = a * v.w + b;
    ((float4*)y)[i4] = r;
}

// ---------------- fused gn+SiLU+pad -> fp16 padded input --------------------
__global__ void gnpad_kernel(const float* __restrict__ in, __half* __restrict__ pad,
                             const float* __restrict__ sc, const float* __restrict__ bi) {
    int idx = blockIdx.x * 256 + threadIdx.x;
    if (idx >= CCH * PAD_PER_C) return;
    int ci = idx / PAD_PER_C, r = idx - ci * PAD_PER_C;
    int tp = r / 1156, r2 = r - tp * 1156;
    int hp = r2 / 34, wp = r2 - hp * 34;
    int t = tp - 2; t = t < 0 ? 0 : t;
    int h = hp - 1; h = h < 0 ? 0 : (h > 31 ? 31 : h);
    int w = wp - 1; w = w < 0 ? 0 : (w > 31 ? 31 : w);
    int g = ci >> 4;
    float a = sc[ci] * g_rstd[g];
    float b = bi[ci] - g_mean[g] * a;
    float v = a * in[(size_t)ci * S_TOT + t * 1024 + h * 32 + w] + b;
    v = v / (1.f + expf(-v));
    pad[idx] = __float2half(v);
}

// ---------------- per-k offset table for the conv B gather ------------------
__global__ void offb_kernel() {
    int k = blockIdx.x * 256 + threadIdx.x;
    if (k >= KDIM) return;
    int ci = k / 27, tap = k - ci * 27;
    int kd = tap / 9, r2 = tap - kd * 9;
    int kh = r2 / 3, kw = r2 - kh * 3;
    g_offB[k] = ci * PAD_PER_C + kd * 1156 + kh * 34 + kw;
}

// ---------------- weight fragment pack: w[co][k] -> fp16 A-fragment images --
__global__ void wfrag_kernel(const float* __restrict__ w, uint32_t* __restrict__ dst) {
    int idx = blockIdx.x * 256 + threadIdx.x;
    if (idx >= KDIM * CCH / 2) return;
    int reg = idx & 3, lane = (idx >> 2) & 31;
    int r2 = idx >> 7;
    int mtile = r2 & 7, ks = (r2 >> 3) & 1;
    int ktm = r2 >> 4;
    int kt = ktm % KT32, mt = ktm / KT32;
    int m = mt * 128 + mtile * 16 + (reg & 1) * 8 + (lane >> 2);
    int k = kt * 32 + ks * 16 + (reg >> 1) * 8 + 2 * (lane & 3);
    const float* src = &w[(size_t)m * KDIM + k];
    dst[idx] = f2h2(src[0], src[1]);
}

// ---------------- Conv3d implicit GEMM, fp16 m16n8k16, half input ----------
__global__ void __launch_bounds__(256, 2)
conv_hmma_kernel(const __half* __restrict__ pad, const uint32_t* __restrict__ wfr,
                 const float* __restrict__ bias, const float* __restrict__ resid,
                 float* __restrict__ out) {
    __shared__ __align__(16) uint32_t Asm[2][2048];
    __shared__ __align__(16) uint32_t Bsm[2][2112];
    const int tid = threadIdx.x, lane = tid & 31, wid = tid >> 5;
    const int tig = lane & 3, grp = lane >> 2;
    const int mt0 = (wid >> 2) * 4, nt0 = (wid & 3) * 4;
    const int mw = (wid >> 2) * 64, nw = (wid & 3) * 32;
    const int n0 = blockIdx.x * 128, m0 = blockIdx.y * 128;
    const int mt = blockIdx.y;
    const int t = n0 >> 10, h0 = (n0 >> 5) & 31;
    const int kp = tid >> 5;

    int sb[4];
#pragma unroll
    for (int r = 0; r < 4; r++) sb[r] = t * 1156 + (h0 + r) * 34 + lane;
    int boff[4];
#pragma unroll
    for (int r = 0; r < 4; r++) {
        int ntile = r * 4 + (lane >> 3), nin = lane & 7;
        boff[r] = ntile * 66 + (nin * 4 + (kp & 3)) * 2 + (kp >> 2);
    }

    float c[4][4][4];
#pragma unroll
    for (int i = 0; i < 4; i++)
#pragma unroll
        for (int j = 0; j < 4; j++)
#pragma unroll
            for (int q = 0; q < 4; q++) c[i][j][q] = 0.f;

    uint4 areg0, areg1;
    __half brg[4][4];

#define CV_LDG(kt) {                                                         \
    const uint4* asrc = (const uint4*)wfr + (size_t)(mt * KT32 + (kt)) * 512;\
    areg0 = asrc[tid];                                                       \
    areg1 = asrc[tid + 256];                                                 \
    int kb = (kt) * 32 + 2 * kp;                                             \
    int o00 = g_offB[kb], o01 = g_offB[kb + 1];                              \
    int o10 = g_offB[kb + 16], o11 = g_offB[kb + 17];                        \
    _Pragma("unroll")                                                        \
    for (int r = 0; r < 4; r++) {                                            \
        brg[r][0] = pad[o00 + sb[r]];                                        \
        brg[r][1] = pad[o01 + sb[r]];                                        \
        brg[r][2] = pad[o10 + sb[r]];                                        \
        brg[r][3] = pad[o11 + sb[r]];                                        \
    } }

#define CV_STS(buf) {                                                        \
    ((uint4*)&Asm[buf][0])[tid] = areg0;                                     \
    ((uint4*)&Asm[buf][0])[tid + 256] = areg1;                               \
    _Pragma("unroll")                                                        \
    for (int r = 0; r < 4; r++) {                                            \
        Bsm[buf][boff[r]] = pkh2(brg[r][0], brg[r][1]);                      \
        Bsm[buf][boff[r] + 16 * 66] = pkh2(brg[r][2], brg[r][3]);            \
    } }

    CV_LDG(0);
    CV_STS(0);
    __syncthreads();
#pragma unroll 1
    for (int kt = 0; kt < KT32; kt++) {
        int cur = kt & 1;
        if (kt + 1 < KT32) CV_LDG(kt + 1);
        HMMA_TILE(Asm, Bsm, cur, 128);
        if (kt + 1 < KT32) CV_STS(cur ^ 1);
        __syncthreads();
    }

#pragma unroll
    for (int i = 0; i < 4; i++)
#pragma unroll
        for (int half = 0; half < 2; half++) {
            int co = m0 + mw + i * 16 + grp + half * 8;
            float bv = bias[co];
            size_t rowbase = (size_t)co * S_TOT + n0;
#pragma unroll
            for (int j = 0; j < 4; j++) {
                int col = nw + j * 8 + 2 * tig;
                float2 v;
                v.x = c[i][j][half * 2 + 0] + bv;
                v.y = c[i][j][half * 2 + 1] + bv;
                if (resid) {
                    v.x += resid[rowbase + col];
                    v.y += resid[rowbase + col + 1];
                }
                *(float2*)&out[rowbase + col] = v;
            }
        }
}

// ---------------- fp16 HMMA projection GEMM ---------------------------------
// MODE 0: out = half [s][512], +bias   (Q/K/V)
// MODE 1: out = fp32 [c][s], +bias+resid (o-proj; X = O in [d][s] fp32)
template <int MODE>
__global__ void __launch_bounds__(256, 2)
proj_hmma_kernel(const float* __restrict__ X, const float* __restrict__ W,
                 const float* __restrict__ bias, const float* __restrict__ resid,
                 void* __restrict__ outp) {
    __shared__ __align__(16) uint32_t Asm[2][2112];
    __shared__ __align__(16) uint32_t Bsm[2][2112];
    const int tid = threadIdx.x, lane = tid & 31, wid = tid >> 5;
    const int tig = lane & 3, grp = lane >> 2;
    const int mt0 = (wid >> 2) * 4, nt0 = (wid & 3) * 4;
    const int mw = (wid >> 2) * 64, nw = (wid & 3) * 32;
    const int n0 = blockIdx.x * 128, m0 = blockIdx.y * 128;
    const int kp = tid >> 5;

    int aoff[4][2];
#pragma unroll
    for (int r = 0; r < 4; r++) {
        int m = r * 32 + lane;
        int lane_c = (m & 7) * 4 + (kp & 3);
        int reg0 = (kp >> 2) * 2 + ((m >> 3) & 1);
#pragma unroll
        for (int ks = 0; ks < 2; ks++)
            aoff[r][ks] = (ks * 8 + (m >> 4)) * 132 + lane_c * 4 + reg0;
    }
    int boff[4];
#pragma unroll
    for (int r = 0; r < 4; r++) {
        int cc = r * 32 + lane;
        boff[r] = (cc >> 3) * 66 + (cc & 7) * 8 + (kp & 3) * 2 + (kp >> 2);
    }

    float c[4][4][4];
#pragma unroll
    for (int i = 0; i < 4; i++)
#pragma unroll
        for (int j = 0; j < 4; j++)
#pragma unroll
            for (int q = 0; q < 4; q++) c[i][j][q] = 0.f;

    float arg[4][2][2];
    float2 wrg[4][2];

#define PR_LDG(kt) {                                                         \
    int kb = (kt) * 32;                                                      \
    _Pragma("unroll")                                                        \
    for (int ks = 0; ks < 2; ks++) {                                         \
        const float* x0 = &X[(size_t)(kb + ks * 16 + 2 * kp) * S_TOT + m0 + lane]; \
        _Pragma("unroll")                                                    \
        for (int r = 0; r < 4; r++) {                                        \
            arg[r][ks][0] = x0[r * 32];                                      \
            arg[r][ks][1] = x0[S_TOT + r * 32];                              \
        }                                                                    \
    }                                                                        \
    _Pragma("unroll")                                                        \
    for (int r = 0; r < 4; r++) {                                            \
        const float* wp2 = &W[(size_t)(n0 + r * 32 + lane) * 512 + kb + 2 * kp]; \
        wrg[r][0] = *(const float2*)wp2;                                     \
        wrg[r][1] = *(const float2*)(wp2 + 16);                              \
    } }

#define PR_STS(buf) {                                                        \
    _Pragma("unroll")                                                        \
    for (int r = 0; r < 4; r++) {                                            \
        Asm[buf][aoff[r][0]] = f2h2(arg[r][0][0], arg[r][0][1]);             \
        Asm[buf][aoff[r][1]] = f2h2(arg[r][1][0], arg[r][1][1]);             \
        Bsm[buf][boff[r]] = f2h2(wrg[r][0].x, wrg[r][0].y);                  \
        Bsm[buf][boff[r] + 16 * 66] = f2h2(wrg[r][1].x, wrg[r][1].y);        \
    } }

    PR_LDG(0);
    PR_STS(0);
    __syncthreads();
#pragma unroll 1
    for (int kt = 0; kt < 16; kt++) {
        int cur = kt & 1;
        if (kt + 1 < 16) PR_LDG(kt + 1);
        HMMA_TILE(Asm, Bsm, cur, 132);
        if (kt + 1 < 16) PR_STS(cur ^ 1);
        __syncthreads();
    }

#pragma unroll
    for (int i = 0; i < 4; i++)
#pragma unroll
        for (int half = 0; half < 2; half++) {
            int srow = m0 + mw + i * 16 + grp + half * 8;
#pragma unroll
            for (int j = 0; j < 4; j++) {
                int ccol = n0 + nw + j * 8 + 2 * tig;
                float v0 = c[i][j][half * 2 + 0];
                float v1 = c[i][j][half * 2 + 1];
                if (MODE == 0) {
                    float2 bv = *(const float2*)&bias[ccol];
                    uint32_t* oh = (uint32_t*)outp;
                    oh[((size_t)srow * 512 + ccol) >> 1] = f2h2(v0 + bv.x, v1 + bv.y);
                } else {
                    float* of = (float*)outp;
                    size_t i0 = (size_t)ccol * S_TOT + srow;
                    size_t i1 = (size_t)(ccol + 1) * S_TOT + srow;
                    of[i0] = v0 + bias[ccol] + resid[i0];
                    of[i1] = v1 + bias[ccol + 1] + resid[i1];
                }
            }
        }
}

// ---------------- Scores fp16: S = scale * Q K^T (frame-causal skip) --------
// Qh/Kh: half [s][512] viewed as uint32 [s][256] (k-pairs).
__global__ void __launch_bounds__(256, 2)
scores_f16_kernel(const uint32_t* __restrict__ Qh, const uint32_t* __restrict__ Kh,
                  float* __restrict__ S) {
    const int n0 = blockIdx.x * 128, m0 = blockIdx.y * 128;
    if ((n0 >> 10) > (m0 >> 10)) return;
    __shared__ __align__(16) uint32_t Asm[2][2112];
    __shared__ __align__(16) uint32_t Bsm[2][2112];
    const int tid = threadIdx.x, lane = tid & 31, wid = tid >> 5;
    const int tig = lane & 3, grp = lane >> 2;
    const int mt0 = (wid >> 2) * 4, nt0 = (wid & 3) * 4;
    const int mw = (wid >> 2) * 64, nw = (wid & 3) * 32;
    const int kp = tid >> 5;

    int aoff[4][2];
#pragma unroll
    for (int r = 0; r < 4; r++) {
        int m = r * 32 + lane;
        int lane_c = (m & 7) * 4 + (kp & 3);
        int reg0 = (kp >> 2) * 2 + ((m >> 3) & 1);
#pragma unroll
        for (int ks = 0; ks < 2; ks++)
            aoff[r][ks] = (ks * 8 + (m >> 4)) * 132 + lane_c * 4 + reg0;
    }
    int boff[4];
#pragma unroll
    for (int r = 0; r < 4; r++) {
        int cc = r * 32 + lane;
        boff[r] = (cc >> 3) * 66 + (cc & 7) * 8 + (kp & 3) * 2 + (kp >> 2);
    }

    float c[4][4][4];
#pragma unroll
    for (int i = 0; i < 4; i++)
#pragma unroll
        for (int j = 0; j < 4; j++)
#pragma unroll
            for (int q = 0; q < 4; q++) c[i][j][q] = 0.f;

    uint32_t aq[4][2], bq[4][2];

#define SF_LDG(kt) {                                                         \
    int kb2 = (kt) * 16 + kp;                                                \
    _Pragma("unroll")                                                        \
    for (int r = 0; r < 4; r++) {                                            \
        const uint32_t* qp = &Qh[(size_t)(m0 + r * 32 + lane) * 256 + kb2];  \
        aq[r][0] = qp[0]; aq[r][1] = qp[8];                                  \
        const uint32_t* kp2 = &Kh[(size_t)(n0 + r * 32 + lane) * 256 + kb2]; \
        bq[r][0] = kp2[0]; bq[r][1] = kp2[8];                                \
    } }

#define SF_STS(buf) {                                                        \
    _Pragma("unroll")                                                        \
    for (int r = 0; r < 4; r++) {                                            \
        Asm[buf][aoff[r][0]] = aq[r][0];                                     \
        Asm[buf][aoff[r][1]] = aq[r][1];                                     \
        Bsm[buf][boff[r]] = bq[r][0];                                        \
        Bsm[buf][boff[r] + 16 * 66] = bq[r][1];                              \
    } }

    SF_LDG(0);
    SF_STS(0);
    __syncthreads();
#pragma unroll 1
    for (int kt = 0; kt < 16; kt++) {
        int cur = kt & 1;
        if (kt + 1 < 16) SF_LDG(kt + 1);
        HMMA_TILE(Asm, Bsm, cur, 132);
        if (kt + 1 < 16) SF_STS(cur ^ 1);
        __syncthreads();
    }

    const float scale = 0.04419417382415922f;  // 512^-0.5
#pragma unroll
    for (int i = 0; i < 4; i++)
#pragma unroll
        for (int half = 0; half < 2; half++) {
            int row = mw + i * 16 + grp + half * 8;
            size_t rowbase = (size_t)(m0 + row) * S_TOT + n0;
#pragma unroll
            for (int j = 0; j < 4; j++) {
                int col = nw + j * 8 + 2 * tig;
                float2 v;
                v.x = c[i][j][half * 2 + 0] * scale;
                v.y = c[i][j][half * 2 + 1] * scale;
                *(float2*)&S[rowbase + col] = v;
            }
        }
}

// ---------------- PV: O = P(prefix) * V (tf32; V in half), out [d][s] -------
__global__ void __launch_bounds__(256, 2)
pv_mma_kernel(const float* __restrict__ P, const __half* __restrict__ V,
              float* __restrict__ out) {
    const int n0 = blockIdx.x * 128, m0 = blockIdx.y * 128;
    __shared__ uint32_t As[2][16][136];
    __shared__ uint32_t Bs[2][16][136];
    const int tid = threadIdx.x, lane = tid & 31, wid = tid >> 5;
    const int tig = lane & 3, grp = lane >> 2;
    const int mw = (wid >> 2) * 64, nw = (wid & 3) * 32;
    const int mm = tid >> 1, kk0 = (tid & 1) * 8;
    const int vrow = tid >> 4, vcol = (tid & 15) * 8;

    float c[4][4][4];
#pragma unroll
    for (int i = 0; i < 4; i++)
#pragma unroll
        for (int j = 0; j < 4; j++)
#pragma unroll
            for (int q = 0; q < 4; q++) c[i][j][q] = 0.f;

    float4 ap0, ap1;
    uint4 hv;

#define PV_LDG(kt) {                                                         \
    int kb = (kt) * 16;                                                      \
    const float* pp = &P[(size_t)(m0 + mm) * S_TOT + kb + kk0];              \
    ap0 = *(const float4*)pp; ap1 = *(const float4*)(pp + 4);                \
    hv = *(const uint4*)&V[(size_t)(kb + vrow) * 512 + n0 + vcol]; }

#define PV_STS(buf) {                                                        \
    As[buf][kk0 + 0][mm] = f2tf32(ap0.x);                                    \
    As[buf][kk0 + 1][mm] = f2tf32(ap0.y);                                    \
    As[buf][kk0 + 2][mm] = f2tf32(ap0.z);                                    \
    As[buf][kk0 + 3][mm] = f2tf32(ap0.w);                                    \
    As[buf][kk0 + 4][mm] = f2tf32(ap1.x);                                    \
    As[buf][kk0 + 5][mm] = f2tf32(ap1.y);                                    \
    As[buf][kk0 + 6][mm] = f2tf32(ap1.z);                                    \
    As[buf][kk0 + 7][mm] = f2tf32(ap1.w);                                    \
    __half2 h0 = *(__half2*)&hv.x, h1 = *(__half2*)&hv.y;                    \
    __half2 h2 = *(__half2*)&hv.z, h3 = *(__half2*)&hv.w;                    \
    uint4 s0, s1;                                                            \
    s0.x = f2tf32(__low2float(h0));  s0.y = f2tf32(__high2float(h0));        \
    s0.z = f2tf32(__low2float(h1));  s0.w = f2tf32(__high2float(h1));        \
    s1.x = f2tf32(__low2float(h2));  s1.y = f2tf32(__high2float(h2));        \
    s1.z = f2tf32(__low2float(h3));  s1.w = f2tf32(__high2float(h3));        \
    *(uint4*)&Bs[buf][vrow][vcol] = s0;                                      \
    *(uint4*)&Bs[buf][vrow][vcol + 4] = s1; }

    PV_LDG(0);
    PV_STS(0);
    __syncthreads();
    const int KT = ((m0 >> 10) + 1) * 64;  // allowed prefix / 16
#pragma unroll 1
    for (int kt = 0; kt < KT; kt++) {
        int cur = kt & 1;
        if (kt + 1 < KT) PV_LDG(kt + 1);
        MMA_COMPUTE(cur);
        if (kt + 1 < KT) PV_STS(cur ^ 1);
        __syncthreads();
    }

    // write transposed: out[d][s]  (feeds MODE-1 proj as its k-major A)
#pragma unroll
    for (int i = 0; i < 4; i++)
#pragma unroll
        for (int half = 0; half < 2; half++) {
            int row = m0 + mw + i * 16 + grp + half * 8;  // q (s)
#pragma unroll
            for (int j = 0; j < 4; j++) {
                int col = n0 + nw + j * 8 + 2 * tig;      // d
                out[(size_t)col * S_TOT + row] = c[i][j][half * 2 + 0];
                out[(size_t)(col + 1) * S_TOT + row] = c[i][j][half * 2 + 1];
            }
        }
}

// ---------------- Row softmax over allowed prefix ---------------------------
__global__ void softmax_kernel(float* __restrict__ S) {
    __shared__ float red[256];
    int q = blockIdx.x;
    int L = ((q >> 10) + 1) << 10;
    int n = L >> 8;
    float* row = S + (size_t)q * S_TOT;
    float v[32];
    float mx = -1e30f;
#pragma unroll
    for (int i = 0; i < 32; i++)
        if (i < n) { v[i] = row[i * 256 + threadIdx.x]; mx = fmaxf(mx, v[i]); }
    red[threadIdx.x] = mx;
    __syncthreads();
    for (int off = 128; off > 0; off >>= 1) {
        if (threadIdx.x < off) red[threadIdx.x] = fmaxf(red[threadIdx.x], red[threadIdx.x + off]);
        __syncthreads();
    }
    mx = red[0];
    __syncthreads();
    float s = 0.f;
#pragma unroll
    for (int i = 0; i < 32; i++)
        if (i < n) { v[i] = expf(v[i] - mx); s += v[i]; }
    red[threadIdx.x] = s;
    __syncthreads();
    for (int off = 128; off > 0; off >>= 1) {
        if (threadIdx.x < off) red[threadIdx.x] += red[threadIdx.x + off];
        __syncthreads();
    }
    float inv = 1.f / red[0];
#pragma unroll
    for (int i = 0; i < 32; i++)
        if (i < n) row[i * 256 + threadIdx.x] = v[i] * inv;
}

// ---------------------------- launcher -------------------------------------
extern "C" void kernel_launch(void* const* d_in, const int* in_sizes, int n_in,
                              void* d_out, int out_size) {
    (void)in_sizes; (void)n_in; (void)out_size;
    const float* x      = (const float*)d_in[0];
    const float* r0_n1s = (const float*)d_in[1];
    const float* r0_n1b = (const float*)d_in[2];
    const float* r0_w1  = (const float*)d_in[3];
    const float* r0_b1  = (const float*)d_in[4];
    const float* r0_n2s = (const float*)d_in[5];
    const float* r0_n2b = (const float*)d_in[6];
    const float* r0_w2  = (const float*)d_in[7];
    const float* r0_b2  = (const float*)d_in[8];
    const float* r1_n1s = (const float*)d_in[9];
    const float* r1_n1b = (const float*)d_in[10];
    const float* r1_w1  = (const float*)d_in[11];
    const float* r1_b1  = (const float*)d_in[12];
    const float* r1_n2s = (const float*)d_in[13];
    const float* r1_n2b = (const float*)d_in[14];
    const float* r1_w2  = (const float*)d_in[15];
    const float* r1_b2  = (const float*)d_in[16];
    const float* a_gns  = (const float*)d_in[17];
    const float* a_gnb  = (const float*)d_in[18];
    const float* wq = (const float*)d_in[19];
    const float* bq = (const float*)d_in[20];
    const float* wk = (const float*)d_in[21];
    const float* bk = (const float*)d_in[22];
    const float* wv = (const float*)d_in[23];
    const float* bv = (const float*)d_in[24];
    const float* wo = (const float*)d_in[25];
    const float* bo = (const float*)d_in[26];
    float* out = (float*)d_out;

    float *b0, *b1, *b2, *qb, *kb, *vb, *sc, *padb;
    uint32_t* wfrb;
    cudaGetSymbolAddress((void**)&b0, g_buf0);
    cudaGetSymbolAddress((void**)&b1, g_buf1);
    cudaGetSymbolAddress((void**)&b2, g_buf2);
    cudaGetSymbolAddress((void**)&qb, g_q);
    cudaGetSymbolAddress((void**)&kb, g_k);
    cudaGetSymbolAddress((void**)&vb, g_v);
    cudaGetSymbolAddress((void**)&sc, g_scores);
    cudaGetSymbolAddress((void**)&padb, g_pad);
    cudaGetSymbolAddress((void**)&wfrb, g_wfr);
    __half* padh = (__half*)padb;

    const int padblocks = (CCH * PAD_PER_C + 255) / 256;
    const int wfrblocks = (KDIM * CCH / 2) / 256;  // 13824
    dim3 cgrid(64, 4);    // conv: n-tiles (128 spatial), m-tiles (128 co)
    dim3 prgrid(4, 64);   // proj: n-tiles (128 ch), m-tiles (128 s)

#define GN_STATS(ptr) do { \
    gn_part_kernel<<<256, 256>>>(ptr); \
    gn_fin_kernel<<<1, 32>>>(); } while (0)

    offb_kernel<<<(KDIM + 255) / 256, 256>>>();

    // ---- resnet block 0 ----
    GN_STATS(x);
    gnpad_kernel<<<padblocks, 256>>>(x, padh, r0_n1s, r0_n1b);
    wfrag_kernel<<<wfrblocks, 256>>>(r0_w1, wfrb);
    conv_hmma_kernel<<<cgrid, 256>>>(padh, wfrb, r0_b1, nullptr, b1);
    GN_STATS(b1);
    gnpad_kernel<<<padblocks, 256>>>(b1, padh, r0_n2s, r0_n2b);
    wfrag_kernel<<<wfrblocks, 256>>>(r0_w2, wfrb);
    conv_hmma_kernel<<<cgrid, 256>>>(padh, wfrb, r0_b2, x, b2);  // b2 = resnet0 out

    // ---- causal frame attention ----
    GN_STATS(b2);
    gn_apply_kernel<<<4096, 256>>>(b2, b0, a_gns, a_gnb);      // b0 = xn [c][s] fp32
    proj_hmma_kernel<0><<<prgrid, 256>>>(b0, wq, bq, nullptr, qb);  // half [s][512]
    proj_hmma_kernel<0><<<prgrid, 256>>>(b0, wk, bk, nullptr, kb);
    proj_hmma_kernel<0><<<prgrid, 256>>>(b0, wv, bv, nullptr, vb);
    scores_f16_kernel<<<dim3(64, 64), 256>>>((const uint32_t*)qb, (const uint32_t*)kb, sc);
    softmax_kernel<<<8192, 256>>>(sc);
    pv_mma_kernel<<<dim3(4, 64), 256>>>(sc, (const __half*)vb, b1);  // b1 = O [d][s]
    proj_hmma_kernel<1><<<prgrid, 256>>>(b1, wo, bo, b2, b0);  // b0 = attn out [c][s]

    // ---- resnet block 1 ----
    GN_STATS(b0);
    gnpad_kernel<<<padblocks, 256>>>(b0, padh, r1_n1s, r1_n1b);
    wfrag_kernel<<<wfrblocks, 256>>>(r1_w1, wfrb);
    conv_hmma_kernel<<<cgrid, 256>>>(padh, wfrb, r1_b1, nullptr, b2);
    GN_STATS(b2);
    gnpad_kernel<<<padblocks, 256>>>(b2, padh, r1_n2s, r1_n2b);
    wfrag_kernel<<<wfrblocks, 256>>>(r1_w2, wfrb);
    conv_hmma_kernel<<<cgrid, 256>>>(padh, wfrb, r1_b2, b0, out);
}